// round 17
// baseline (speedup 1.0000x reference)
#include <cuda_runtime.h>
#include <cstdint>

// Problem constants
#define NB   8
#define TPD  2048
#define ED   4096
#define TD   16384
#define VD   17
#define OUTROWS 131072
#define KSP  4              // K splits for the GEMM
#define KC   (ED / KSP)     // 1024 K per block
#define KT   32             // K floats per pipeline stage (128B rows)
#define NSTG (KC / KT)      // 32 stages
#define MTIL 256            // M rows per MMA block
#define RMAX 16384

typedef unsigned long long ull;

// Scratch (device globals)
__device__ float g_WeffJ[64 * ED];      // [j=s0*8+s][e], tf32-rounded
__device__ float g_beff[8];             // includes b2
__device__ int   g_entry[NB * RMAX];    // per-batch rank-ordered: (utpidx<<14)|t
__device__ int   g_utp[NB * TPD];       // per-batch unique active tp list
__device__ int   g_count8[NB];          // 8 * per-batch masked count
__device__ int   g_ucount[NB];          // per-batch unique active tp count
__device__ float g_C[(size_t)KSP * NB * TPD * 64];  // GEMM partials, utp-indexed (16MB)

// ---------------------------------------------------------------------------
// helpers
// ---------------------------------------------------------------------------
__device__ __forceinline__ void ldgsts16(void* dst, const void* src) {
    unsigned saddr = (unsigned)__cvta_generic_to_shared(dst);
    asm volatile("cp.async.cg.shared.global [%0], [%1], 16;\n" :: "r"(saddr), "l"(src));
}
__device__ __forceinline__ void cp_commit() {
    asm volatile("cp.async.commit_group;\n" ::: "memory");
}
template <int N>
__device__ __forceinline__ void cp_wait() {
    asm volatile("cp.async.wait_group %0;\n" :: "n"(N) : "memory");
}
__device__ __forceinline__ float to_tf32_rna(float f) {
    unsigned u;
    asm("cvt.rna.tf32.f32 %0, %1;" : "=r"(u) : "f"(f));
    return __uint_as_float(u);
}
// XOR-swizzled smem float index: 32-float (128B) rows, 16B chunk swizzle
__device__ __forceinline__ int aidx(int r, int ce) {
    return r * 32 + ((((ce >> 2) ^ (r & 7)) << 2) | (ce & 3));
}
__device__ __forceinline__ void mma_tf32(float* c, const unsigned* a,
                                         unsigned b0, unsigned b1) {
    asm volatile(
        "mma.sync.aligned.m16n8k8.row.col.f32.tf32.tf32.f32 "
        "{%0,%1,%2,%3}, {%4,%5,%6,%7}, {%8,%9}, {%0,%1,%2,%3};"
        : "+f"(c[0]), "+f"(c[1]), "+f"(c[2]), "+f"(c[3])
        : "r"(a[0]), "r"(a[1]), "r"(a[2]), "r"(a[3]), "r"(b0), "r"(b1));
}

// ---------------------------------------------------------------------------
// K01 fused, 1024 threads/block:
//   blocks [0,8): prep v2 — argmax, masked compaction with unique-tp list.
//     Per thread 1 tp (8 t's), dual warp/block scans (rank, utp), 2 passes.
//   blocks [8,264): WeffJ rows for 16 e-values each (+beff at block 8)
// ---------------------------------------------------------------------------
__global__ __launch_bounds__(1024) void k01(const float* __restrict__ W1,
                                            const float* __restrict__ W2,
                                            const float* __restrict__ b1,
                                            const float* __restrict__ b2,
                                            const int* __restrict__ value,
                                            const int* __restrict__ depth) {
    int bid = blockIdx.x;
    int tid = threadIdx.x;

    if (bid >= 8) {
        // ---- WeffJ: 16 e-values per block ----
        __shared__ __align__(16) float w2s[512];
        __shared__ __align__(16) float w1r[16][512];
        int e0 = (bid - 8) * 16;
        if (tid < 128) ((float4*)w2s)[tid] = ((const float4*)W2)[tid];
        ((float4*)&w1r[0][0])[tid]        = ((const float4*)(W1 + (size_t)e0 * 512))[tid];
        ((float4*)&w1r[0][0])[tid + 1024] = ((const float4*)(W1 + (size_t)e0 * 512))[tid + 1024];
        __syncthreads();
        int sub = tid >> 6;       // which e (0..15)
        int t64 = tid & 63;
        int s0 = t64 >> 3, s = t64 & 7;
        int e = e0 + sub;
        float acc = 0.f;
#pragma unroll
        for (int c = 0; c < 64; c++) acc += w1r[sub][c * 8 + s0] * w2s[c * 8 + s];
        g_WeffJ[(size_t)(s0 * 8 + s) * ED + e] = to_tf32_rna(acc);
        if (bid == 8 && tid < 8) {
            float a = 0.f;
#pragma unroll
            for (int c = 0; c < 64; c++) a += b1[c] * w2s[c * 8 + tid];
            g_beff[tid] = a + b2[0];
        }
    } else {
        // ---- prep v2: batch n ----
        int n = bid;
        const int* dep = depth + n * TD;
        const int* val = value + n * TD;
        __shared__ int s_idx;
        __shared__ int wsR[32], wsU[32];
        __shared__ int sb_r, sb_u, ptR, ptU;
        int lane = tid & 31, wid = tid >> 5;  // 32 warps

        int maxv = dep[TD - 1];
        if (tid == 0) { s_idx = TD; sb_r = 0; sb_u = 0; }
        __syncthreads();
        for (int t0 = tid * 4; t0 < TD; t0 += 4096) {
            int4 d = *(const int4*)(dep + t0);
            int prev = (t0 == 0) ? (maxv - 1) : dep[t0 - 1];
            if (d.x == maxv && prev < maxv) atomicMin(&s_idx, t0);
            if (d.y == maxv && d.x < maxv) atomicMin(&s_idx, t0 + 1);
            if (d.z == maxv && d.y < maxv) atomicMin(&s_idx, t0 + 2);
            if (d.w == maxv && d.z < maxv) atomicMin(&s_idx, t0 + 3);
        }
        __syncthreads();
        int idx = s_idx;

        for (int pass = 0; pass < 2; pass++) {
            int tp = pass * 1024 + tid;
            int t0 = tp * 8;
            int4 va = *(const int4*)(val + t0);
            int4 vb = *(const int4*)(val + t0 + 4);
            int vj[8] = {va.x, va.y, va.z, va.w, vb.x, vb.y, vb.z, vb.w};
            unsigned mb = 0;
            int cnt = 0;
#pragma unroll
            for (int j = 0; j < 8; j++) {
                bool m = (t0 + j < idx) && (vj[j] == 2);
                mb |= ((unsigned)m) << j;
                cnt += (int)m;
            }
            int flag = (cnt > 0) ? 1 : 0;
            int vR = cnt, vU = flag;
#pragma unroll
            for (int o = 1; o < 32; o <<= 1) {
                int uR = __shfl_up_sync(0xffffffffu, vR, o);
                int uU = __shfl_up_sync(0xffffffffu, vU, o);
                if (lane >= o) { vR += uR; vU += uU; }
            }
            if (lane == 31) { wsR[wid] = vR; wsU[wid] = vU; }
            __syncthreads();
            if (wid == 0) {
                int w = wsR[lane], wi = w;
#pragma unroll
                for (int o = 1; o < 32; o <<= 1) {
                    int uu = __shfl_up_sync(0xffffffffu, wi, o);
                    if (lane >= o) wi += uu;
                }
                wsR[lane] = wi - w;
                if (lane == 31) ptR = wi;
            } else if (wid == 1) {
                int w = wsU[lane], wi = w;
#pragma unroll
                for (int o = 1; o < 32; o <<= 1) {
                    int uu = __shfl_up_sync(0xffffffffu, wi, o);
                    if (lane >= o) wi += uu;
                }
                wsU[lane] = wi - w;
                if (lane == 31) ptU = wi;
            }
            __syncthreads();
            int r = sb_r + wsR[wid] + vR - cnt;
            int u = sb_u + wsU[wid] + vU - flag;
            if (flag) g_utp[n * TPD + u] = tp;
#pragma unroll
            for (int j = 0; j < 8; j++) {
                if ((mb >> j) & 1u) {
                    g_entry[n * RMAX + r] = (u << 14) | (t0 + j);
                    r++;
                }
            }
            __syncthreads();
            if (tid == 0) { sb_r += ptR; sb_u += ptU; }
            __syncthreads();
        }
        if (tid == 0) { g_count8[n] = 8 * sb_r; g_ucount[n] = sb_u; }
    }
}

// ---------------------------------------------------------------------------
// K3: dense-compacted tf32 mma GEMM (R13-proven core) + hidden tail-fill.
//   mt in [0,8): MMA block — rows gathered via g_utp (active tps only):
//     C_part[ksp][n][mt*256..+256][0..64) = X[gathered 256 rows, KC] · WeffJ^T
//   mt in [8,16): fill chunk (mt-8)*4+ksp of batch n's tail
//     (flattened floats [count8*17, OUTROWS*17), f4-aligned with scalar head).
// ---------------------------------------------------------------------------
__global__ __launch_bounds__(128) void k3_mma(const float* __restrict__ x,
                                              const float* __restrict__ W3,
                                              const float* __restrict__ b2,
                                              float* __restrict__ out) {
    int mt = blockIdx.x, ksp = blockIdx.y, n = blockIdx.z;
    int tid = threadIdx.x;

    if (mt >= 8) {
        // ---- tail fill ----
        __shared__ float w3s[VD];
        if (tid < VD) w3s[tid] = W3[tid];
        __syncthreads();
        float bv = b2[0];
        unsigned count8 = (unsigned)g_count8[n];
        unsigned fstart = count8 * VD;
        const unsigned fend = (unsigned)OUTROWS * VD;  // 2228224, mult of 4
        unsigned a0 = (fstart + 3u) & ~3u;
        if (a0 > fend) a0 = fend;
        int chunk = (mt - 8) * 4 + ksp;  // 0..31
        unsigned f4lo = a0 >> 2, f4hi = fend >> 2;
        unsigned per = (f4hi - f4lo + 31u) >> 5;
        unsigned lo = f4lo + (unsigned)chunk * per;
        unsigned hi = lo + per; if (hi > f4hi) hi = f4hi;
        float* ob = out + (size_t)n * OUTROWS * VD;
        if (chunk == 0) {
            for (unsigned p = fstart + tid; p < a0; p += 128) ob[p] = bv * w3s[p % VD];
        }
        for (unsigned F = lo + tid; F < hi; F += 128) {
            float4 o;
#pragma unroll
            for (int c = 0; c < 4; c++) {
                unsigned p = F * 4 + c;
                ((float*)&o)[c] = bv * w3s[p % VD];
            }
            *(float4*)(ob + (size_t)F * 4) = o;
        }
        return;
    }

    // ---- MMA block ----
    int ucount = g_ucount[n];
    if (mt * MTIL >= ucount) return;
    int w = tid >> 5, lane = tid & 31;
    int gid = lane >> 2, tig = lane & 3;

    extern __shared__ __align__(16) float dsm[];
    float* As = dsm;                 // [2][256*32] = 65536B
    float* Bs = dsm + 2 * 256 * 32;  // [2][64*32]  = 16384B
    __shared__ int stp_s[MTIL];

    // row gather metadata
#pragma unroll
    for (int i = 0; i < 2; i++) {
        int li = tid + 128 * i;
        int gr = mt * MTIL + li;
        stp_s[li] = (gr < ucount) ? g_utp[n * TPD + gr] : 0;
    }
    __syncthreads();

    const float* xb = x + (size_t)n * TPD * ED + ksp * KC;
    const float* wb = g_WeffJ + ksp * KC;

    auto load_stage = [&](int st, int b) {
        const float* xs = xb + st * KT;
        float* Ab = As + b * 256 * 32;
#pragma unroll
        for (int p = 0; p < 16; p++) {
            int g = p * 128 + tid;
            int r = g >> 3, c = g & 7;          // 8 x 16B chunks per 128B row
            ldgsts16(&Ab[r * 32 + ((c ^ (r & 7)) << 2)],
                     xs + (size_t)stp_s[r] * ED + c * 4);
        }
        const float* ws = wb + st * KT;
        float* Bb = Bs + b * 64 * 32;
#pragma unroll
        for (int p = 0; p < 4; p++) {
            int g = p * 128 + tid;
            int r = g >> 3, c = g & 7;
            ldgsts16(&Bb[r * 32 + ((c ^ (r & 7)) << 2)],
                     ws + (size_t)r * ED + c * 4);
        }
        cp_commit();
    };

    load_stage(0, 0);

    float acc[4][8][4];
#pragma unroll
    for (int i = 0; i < 4; i++)
#pragma unroll
        for (int nj = 0; nj < 8; nj++)
#pragma unroll
            for (int q = 0; q < 4; q++) acc[i][nj][q] = 0.f;

    for (int st = 0; st < NSTG; st++) {
        int b = st & 1;
        if (st + 1 < NSTG) {
            load_stage(st + 1, b ^ 1);
            cp_wait<1>();
        } else {
            cp_wait<0>();
        }
        __syncthreads();

        const float* Ab = As + b * 256 * 32;
        const float* Bb = Bs + b * 64 * 32;
#pragma unroll
        for (int kk = 0; kk < 4; kk++) {
            int c0 = kk * 8 + tig;
            unsigned a[4][4];
#pragma unroll
            for (int i = 0; i < 4; i++) {
                int rl = w * 64 + i * 16 + gid;
                int rh = rl + 8;
                a[i][0] = __float_as_uint(Ab[aidx(rl, c0)]);
                a[i][1] = __float_as_uint(Ab[aidx(rh, c0)]);
                a[i][2] = __float_as_uint(Ab[aidx(rl, c0 + 4)]);
                a[i][3] = __float_as_uint(Ab[aidx(rh, c0 + 4)]);
            }
#pragma unroll
            for (int nj = 0; nj < 8; nj++) {
                int j = nj * 8 + gid;
                unsigned b0 = __float_as_uint(Bb[aidx(j, c0)]);
                unsigned b1 = __float_as_uint(Bb[aidx(j, c0 + 4)]);
#pragma unroll
                for (int i = 0; i < 4; i++)
                    mma_tf32(acc[i][nj], a[i], b0, b1);
            }
        }
        __syncthreads();
    }

    // epilogue: scatter C to g_C[ksp][n][utpidx][64]
    float* cb = g_C + (((size_t)ksp * NB + n) * TPD + (size_t)mt * MTIL) * 64;
#pragma unroll
    for (int i = 0; i < 4; i++) {
        int rl = w * 64 + i * 16 + gid;
#pragma unroll
        for (int nj = 0; nj < 8; nj++) {
            int col = nj * 8 + 2 * tig;
            *(float2*)(cb + (size_t)rl * 64 + col) =
                make_float2(acc[i][nj][0], acc[i][nj][1]);
            *(float2*)(cb + (size_t)(rl + 8) * 64 + col) =
                make_float2(acc[i][nj][2], acc[i][nj][3]);
        }
    }
}

#define K3_SMEM ((2 * 256 * 32 + 2 * 64 * 32) * 4)  // 81920 B

// ---------------------------------------------------------------------------
// K4: heavy rows only (j < count8). Writes flattened [j0*17, jend*17) with
// f4 main + scalar tail at the count8*17 boundary (fill owns the other side).
// ---------------------------------------------------------------------------
__global__ __launch_bounds__(256) void k4_heavy(const float* __restrict__ W3,
                                                float* __restrict__ out) {
    int n = blockIdx.y;
    int count8 = g_count8[n];
    int j0 = blockIdx.x * 256;
    if (j0 >= count8) return;
    int tid = threadIdx.x;
    __shared__ float y2s[256];
    __shared__ float w3s[VD];
    __shared__ float beffs[8];
    if (tid < VD) w3s[tid] = W3[tid];
    if (tid < 8) beffs[tid] = g_beff[tid];
    __syncthreads();

    int j = j0 + tid;
    float acc = 0.f;
    if (j < count8) {
        int e = g_entry[n * RMAX + (j >> 3)];
        int s = j & 7;
        int t = e & 16383;
        int s0 = t & 7;
        int u = e >> 14;
        size_t ci = ((size_t)n * TPD + u) * 64 + s0 * 8 + s;
        acc = beffs[s];
#pragma unroll
        for (int kq = 0; kq < KSP; kq++)
            acc += g_C[(size_t)kq * NB * TPD * 64 + ci];
    }
    y2s[tid] = acc;
    __syncthreads();

    int jend = min(j0 + 256, count8);
    unsigned nfl = (unsigned)(jend - j0) * VD;
    float* ob = out + (size_t)n * OUTROWS * VD + (size_t)j0 * VD;  // j0*17 mult of 4
    unsigned nf4 = nfl >> 2;
    for (unsigned f = tid; f < nf4; f += 256) {
        float4 o;
#pragma unroll
        for (int c = 0; c < 4; c++) {
            unsigned idx = f * 4 + c;
            unsigned jj = idx / VD;
            unsigned vv = idx - jj * VD;
            ((float*)&o)[c] = y2s[jj] * w3s[vv];
        }
        *(float4*)(ob + (size_t)f * 4) = o;
    }
    // scalar tail at the count8 boundary
    for (unsigned p = nf4 * 4 + tid; p < nfl; p += 256) {
        unsigned jj = p / VD, vv = p - jj * VD;
        ob[p] = y2s[jj] * w3s[vv];
    }
}

// ---------------------------------------------------------------------------
extern "C" void kernel_launch(void* const* d_in, const int* in_sizes, int n_in,
                              void* d_out, int out_size) {
    const float* x     = (const float*)d_in[0];
    const int*   value = (const int*)d_in[1];   // jax x64-off: int32
    const int*   depth = (const int*)d_in[2];
    // d_in[3] = pos, unused
    const float* W1    = (const float*)d_in[4];
    const float* b1    = (const float*)d_in[5];
    const float* W2    = (const float*)d_in[6];
    const float* b2    = (const float*)d_in[7];
    const float* W3    = (const float*)d_in[8];
    float* out = (float*)d_out;

    cudaFuncSetAttribute(k3_mma, cudaFuncAttributeMaxDynamicSharedMemorySize,
                         K3_SMEM);

    k01<<<264, 1024>>>(W1, W2, b1, b2, value, depth);
    k3_mma<<<dim3(16, KSP, NB), 128, K3_SMEM>>>(x, W3, b2, out);
    k4_heavy<<<dim3(512, NB), 256>>>(W3, out);
}